// round 6
// baseline (speedup 1.0000x reference)
#include <cuda_runtime.h>
#include <cuda_bf16.h>
#include <cstdint>

// Problem shape (fixed): pred [16,4,512,512] f32, target/ME [16,512,512] i32
#define NUM_CLASSES 4
#define IGNORE_INDEX 4
#define HW 262144                 // 512*512 pixels per batch (2^18)
#define NPIX (16 * HW)            // 4,194,304
#define TILE_PIX 1024             // pixels per block tile (divides HW)
#define GRID (NPIX / TILE_PIX)    // 4096 blocks
#define TPB 256                   // each thread computes 4 pixels

#define PRED_TILE_B (TILE_PIX * 4)          // 4096 B per class plane
#define TILE_BYTES  (6 * PRED_TILE_B)       // 24576 B total staged per tile

__device__ float2   g_partials[GRID];   // written unconditionally -> no init kernel
__device__ unsigned g_ticket = 0;       // self-resetting via atomicInc wrap

__device__ __forceinline__ uint32_t smem_u32(const void* p) {
    uint32_t a;
    asm("{ .reg .u64 t; cvta.to.shared.u64 t, %1; cvt.u32.u64 %0, t; }"
        : "=r"(a) : "l"(p));
    return a;
}

__device__ __forceinline__ void bulk_copy_g2s(uint32_t dst_smem, const void* src,
                                              uint32_t bytes, uint32_t mbar) {
    asm volatile(
        "cp.async.bulk.shared::cluster.global.mbarrier::complete_tx::bytes "
        "[%0], [%1], %2, [%3];"
        :: "r"(dst_smem), "l"(src), "r"(bytes), "r"(mbar) : "memory");
}

__device__ __forceinline__ void pixel_nll(float v0, float v1, float v2, float v3,
                                          int t, int me,
                                          float& acc, float& cnt) {
    float m = fmaxf(fmaxf(v0, v1), fmaxf(v2, v3));
    float s = __expf(v0 - m) + __expf(v1 - m) + __expf(v2 - m) + __expf(v3 - m);
    float lse = m + __logf(s);
    int tc = min(t, NUM_CLASSES - 1);
    float vt = (tc == 0) ? v0 : (tc == 1) ? v1 : (tc == 2) ? v2 : v3;
    float nll = lse - vt;
    float w = (me == 0) ? 1.0f : 0.5f;
    bool valid = (t != IGNORE_INDEX);
    acc += valid ? (w * nll) : 0.0f;
    cnt += valid ? 1.0f : 0.0f;
}

__global__ void __launch_bounds__(TPB)
ce_tma_kernel(const float* __restrict__ pred,
              const int* __restrict__ target,
              const int* __restrict__ me,
              float* __restrict__ out) {
    // static smem: 4 pred planes + target + me, 16B-aligned, plus one mbarrier
    __shared__ __align__(16) float  s_pred[4][TILE_PIX];
    __shared__ __align__(16) int    s_tgt[TILE_PIX];
    __shared__ __align__(16) int    s_me[TILE_PIX];
    __shared__ __align__(8)  uint64_t s_mbar;

    const int tid = threadIdx.x;
    const uint32_t mbar = smem_u32(&s_mbar);

    if (tid == 0) {
        asm volatile("mbarrier.init.shared.b64 [%0], 1;" :: "r"(mbar) : "memory");
        asm volatile("fence.proxy.async.shared::cta;" ::: "memory");
    }
    __syncthreads();

    if (tid == 0) {
        // arrive + declare expected transaction bytes, then issue 6 bulk copies
        asm volatile("mbarrier.arrive.expect_tx.shared.b64 _, [%0], %1;"
                     :: "r"(mbar), "r"((uint32_t)TILE_BYTES) : "memory");

        const int P  = blockIdx.x * TILE_PIX;      // global pixel start of tile
        const int b  = P >> 18;                    // batch index (HW = 2^18)
        const int hw = P & (HW - 1);
        const float* pb = pred + (size_t)b * (4 * (size_t)HW) + hw;

        bulk_copy_g2s(smem_u32(&s_pred[0][0]), pb,                      PRED_TILE_B, mbar);
        bulk_copy_g2s(smem_u32(&s_pred[1][0]), pb + HW,                 PRED_TILE_B, mbar);
        bulk_copy_g2s(smem_u32(&s_pred[2][0]), pb + 2 * (size_t)HW,     PRED_TILE_B, mbar);
        bulk_copy_g2s(smem_u32(&s_pred[3][0]), pb + 3 * (size_t)HW,     PRED_TILE_B, mbar);
        bulk_copy_g2s(smem_u32(&s_tgt[0]),     target + P,              PRED_TILE_B, mbar);
        bulk_copy_g2s(smem_u32(&s_me[0]),      me + P,                  PRED_TILE_B, mbar);
    }

    // wait for all 24KB (acquire orders TMA smem writes before our LDS reads)
    {
        uint32_t done;
        asm volatile(
            "{\n\t.reg .pred p;\n\t"
            "mbarrier.try_wait.parity.acquire.cta.shared::cta.b64 p, [%1], 0;\n\t"
            "selp.b32 %0, 1, 0, p;\n\t}"
            : "=r"(done) : "r"(mbar) : "memory");
        if (!done) {
            asm volatile(
                "{\n\t.reg .pred P1;\n\t"
                "WL_%=:\n\t"
                "mbarrier.try_wait.parity.acquire.cta.shared::cta.b64 P1, [%0], 0, 0x989680;\n\t"
                "@P1 bra.uni WD_%=;\n\t"
                "bra.uni WL_%=;\n\t"
                "WD_%=:\n\t}"
                :: "r"(mbar) : "memory");
        }
    }

    // compute: thread t handles tile pixels [4t, 4t+4) — all LDS.128, conflict-free
    float acc = 0.0f, cnt = 0.0f;
    {
        float4 c0 = *reinterpret_cast<const float4*>(&s_pred[0][tid * 4]);
        float4 c1 = *reinterpret_cast<const float4*>(&s_pred[1][tid * 4]);
        float4 c2 = *reinterpret_cast<const float4*>(&s_pred[2][tid * 4]);
        float4 c3 = *reinterpret_cast<const float4*>(&s_pred[3][tid * 4]);
        int4 tg = *reinterpret_cast<const int4*>(&s_tgt[tid * 4]);
        int4 mv = *reinterpret_cast<const int4*>(&s_me[tid * 4]);

        pixel_nll(c0.x, c1.x, c2.x, c3.x, tg.x, mv.x, acc, cnt);
        pixel_nll(c0.y, c1.y, c2.y, c3.y, tg.y, mv.y, acc, cnt);
        pixel_nll(c0.z, c1.z, c2.z, c3.z, tg.z, mv.z, acc, cnt);
        pixel_nll(c0.w, c1.w, c2.w, c3.w, tg.w, mv.w, acc, cnt);
    }

    // warp reduction
    #pragma unroll
    for (int off = 16; off > 0; off >>= 1) {
        acc += __shfl_down_sync(0xFFFFFFFFu, acc, off);
        cnt += __shfl_down_sync(0xFFFFFFFFu, cnt, off);
    }

    // block reduction across 8 warps
    __shared__ float s_acc[8];
    __shared__ float s_cnt[8];
    __shared__ bool  s_last;
    const int wid = tid >> 5;
    const int lid = tid & 31;
    if (lid == 0) { s_acc[wid] = acc; s_cnt[wid] = cnt; }
    __syncthreads();
    if (tid == 0) {
        float a = 0.0f, c = 0.0f;
        #pragma unroll
        for (int w = 0; w < 8; w++) { a += s_acc[w]; c += s_cnt[w]; }
        g_partials[blockIdx.x] = make_float2(a, c);
        __threadfence();
        unsigned old = atomicInc(&g_ticket, GRID - 1);   // wraps to 0 after last block
        s_last = (old == GRID - 1);
    }
    __syncthreads();

    // last-arriving block reduces the 4096 partials and writes the scalar
    if (s_last) {
        float a = 0.0f, c = 0.0f;
        #pragma unroll
        for (int k = 0; k < GRID / TPB; k++) {           // 16 partials per thread
            float2 v = g_partials[tid + k * TPB];
            a += v.x;
            c += v.y;
        }
        #pragma unroll
        for (int off = 16; off > 0; off >>= 1) {
            a += __shfl_down_sync(0xFFFFFFFFu, a, off);
            c += __shfl_down_sync(0xFFFFFFFFu, c, off);
        }
        if (lid == 0) { s_acc[wid] = a; s_cnt[wid] = c; }
        __syncthreads();
        if (tid == 0) {
            float fa = 0.0f, fc = 0.0f;
            #pragma unroll
            for (int w = 0; w < 8; w++) { fa += s_acc[w]; fc += s_cnt[w]; }
            out[0] = fa / fc;
        }
    }
}

extern "C" void kernel_launch(void* const* d_in, const int* in_sizes, int n_in,
                              void* d_out, int out_size) {
    const float* pred   = (const float*)d_in[0];
    const int*   target = (const int*)d_in[1];
    const int*   me     = (const int*)d_in[2];
    float* out = (float*)d_out;

    ce_tma_kernel<<<GRID, TPB>>>(pred, target, me, out);
}

// round 7
// speedup vs baseline: 1.3147x; 1.3147x over previous
#include <cuda_runtime.h>
#include <cuda_bf16.h>

// Problem shape (fixed): pred [16,4,512,512] f32, target/ME [16,512,512] i32
#define NUM_CLASSES 4
#define IGNORE_INDEX 4
#define HW 262144              // 512*512 pixels per batch (2^18)
#define NPIX (16 * HW)         // 4,194,304
#define NVEC (NPIX / 4)        // 1,048,576 float4-groups
#define GRID 912               // 152 SMs x 6 blocks -> exactly ONE wave, no transitions
#define TPB 256

__device__ float2   g_partials[GRID];   // written unconditionally -> no init kernel
__device__ unsigned g_ticket = 0;       // self-resetting via atomicInc wrap

__device__ __forceinline__ void pixel_nll(float v0, float v1, float v2, float v3,
                                          int t, int me,
                                          float& acc, float& cnt) {
    float m = fmaxf(fmaxf(v0, v1), fmaxf(v2, v3));
    float s = __expf(v0 - m) + __expf(v1 - m) + __expf(v2 - m) + __expf(v3 - m);
    float lse = m + __logf(s);
    int tc = min(t, NUM_CLASSES - 1);
    float vt = (tc == 0) ? v0 : (tc == 1) ? v1 : (tc == 2) ? v2 : v3;
    float nll = lse - vt;
    float w = (me == 0) ? 1.0f : 0.5f;
    bool valid = (t != IGNORE_INDEX);
    acc += valid ? (w * nll) : 0.0f;
    cnt += valid ? 1.0f : 0.0f;
}

// 6 blocks/SM (42-reg budget): enough registers to keep all six LDG.128 of an
// iteration in flight, while the persistent grid-stride loop keeps the LSU
// streaming for the whole kernel on a single perfectly-balanced wave.
__global__ void __launch_bounds__(TPB, 6)
ce_persistent_kernel(const float* __restrict__ pred,
                     const int* __restrict__ target,
                     const int* __restrict__ me,
                     float* __restrict__ out) {
    float acc = 0.0f, cnt = 0.0f;

    const int stride = GRID * TPB;                 // 233,472 threads total
    for (int i = blockIdx.x * TPB + threadIdx.x; i < NVEC; i += stride) {
        int p = i << 2;                            // first pixel of this group
        int b = p >> 18;                           // p / HW (HW = 2^18)
        int hw = p & (HW - 1);
        size_t base = (size_t)b * (NUM_CLASSES * (size_t)HW) + hw;

        float4 c0 = *reinterpret_cast<const float4*>(pred + base);
        float4 c1 = *reinterpret_cast<const float4*>(pred + base + HW);
        float4 c2 = *reinterpret_cast<const float4*>(pred + base + 2 * (size_t)HW);
        float4 c3 = *reinterpret_cast<const float4*>(pred + base + 3 * (size_t)HW);
        int4 tg = *reinterpret_cast<const int4*>(target + p);
        int4 mv = *reinterpret_cast<const int4*>(me + p);

        pixel_nll(c0.x, c1.x, c2.x, c3.x, tg.x, mv.x, acc, cnt);
        pixel_nll(c0.y, c1.y, c2.y, c3.y, tg.y, mv.y, acc, cnt);
        pixel_nll(c0.z, c1.z, c2.z, c3.z, tg.z, mv.z, acc, cnt);
        pixel_nll(c0.w, c1.w, c2.w, c3.w, tg.w, mv.w, acc, cnt);
    }

    // warp reduction
    #pragma unroll
    for (int off = 16; off > 0; off >>= 1) {
        acc += __shfl_down_sync(0xFFFFFFFFu, acc, off);
        cnt += __shfl_down_sync(0xFFFFFFFFu, cnt, off);
    }

    // block reduction across 8 warps
    __shared__ float s_acc[8];
    __shared__ float s_cnt[8];
    __shared__ bool  s_last;
    const int wid = threadIdx.x >> 5;
    const int lid = threadIdx.x & 31;
    if (lid == 0) { s_acc[wid] = acc; s_cnt[wid] = cnt; }
    __syncthreads();
    if (threadIdx.x == 0) {
        float a = 0.0f, c = 0.0f;
        #pragma unroll
        for (int w = 0; w < 8; w++) { a += s_acc[w]; c += s_cnt[w]; }
        g_partials[blockIdx.x] = make_float2(a, c);
        __threadfence();
        unsigned old = atomicInc(&g_ticket, GRID - 1);   // wraps to 0 after last block
        s_last = (old == GRID - 1);
    }
    __syncthreads();

    // last-arriving block reduces the 912 partials and writes the scalar
    if (s_last) {
        float a = 0.0f, c = 0.0f;
        #pragma unroll
        for (int k = 0; k < 4; k++) {                    // covers 1024 >= 912 slots
            int idx = threadIdx.x + k * TPB;
            if (idx < GRID) {
                float2 v = g_partials[idx];
                a += v.x;
                c += v.y;
            }
        }
        #pragma unroll
        for (int off = 16; off > 0; off >>= 1) {
            a += __shfl_down_sync(0xFFFFFFFFu, a, off);
            c += __shfl_down_sync(0xFFFFFFFFu, c, off);
        }
        if (lid == 0) { s_acc[wid] = a; s_cnt[wid] = c; }
        __syncthreads();
        if (threadIdx.x == 0) {
            float fa = 0.0f, fc = 0.0f;
            #pragma unroll
            for (int w = 0; w < 8; w++) { fa += s_acc[w]; fc += s_cnt[w]; }
            out[0] = fa / fc;
        }
    }
}

extern "C" void kernel_launch(void* const* d_in, const int* in_sizes, int n_in,
                              void* d_out, int out_size) {
    const float* pred   = (const float*)d_in[0];
    const int*   target = (const int*)d_in[1];
    const int*   me     = (const int*)d_in[2];
    float* out = (float*)d_out;

    ce_persistent_kernel<<<GRID, TPB>>>(pred, target, me, out);
}